// round 2
// baseline (speedup 1.0000x reference)
#include <cuda_runtime.h>

#define MPTS 100000
#define KN   27
#define DD   64
#define CSEM 96

// Scratch (allocation-free rule: __device__ globals)
__device__ float g_Qp[MPTS * DD];
__device__ float g_Kb[MPTS * DD];
__device__ float g_Vb[MPTS * DD];

__device__ __forceinline__ float wsum(float v) {
#pragma unroll
    for (int o = 16; o; o >>= 1) v += __shfl_xor_sync(0xffffffffu, v, o);
    return v;
}
__device__ __forceinline__ float wmax(float v) {
#pragma unroll
    for (int o = 16; o; o >>= 1) v = fmaxf(v, __shfl_xor_sync(0xffffffffu, v, o));
    return v;
}

// ---------------------------------------------------------------------------
// Kernel A: per-point  Q_geo = relu(LN(geo@Wg)),  bdy, Qp=Q@Wq, Kb=Q@Wk, Vb=sem@Wv
// warp per point, weights in dynamic shared memory.
// ---------------------------------------------------------------------------
__global__ void __launch_bounds__(256) kA(
    const float* __restrict__ geo, const float* __restrict__ sem,
    const float* __restrict__ Wg, const float* __restrict__ gam,
    const float* __restrict__ bet, const float* __restrict__ Wb,
    const float* __restrict__ bb, const float* __restrict__ Wq,
    const float* __restrict__ Wk, const float* __restrict__ Wv,
    float* __restrict__ out, long long total)
{
    extern __shared__ float sm[];
    float* sWg = sm;
    float* sWq = sm + 4096;
    float* sWk = sm + 8192;
    float* sWv = sm + 12288;
    float* sWb = sm + 18432;
    float* sGm = sm + 18496;
    float* sBt = sm + 18560;

    for (int i = threadIdx.x; i < 4096; i += 256) {
        sWg[i] = Wg[i]; sWq[i] = Wq[i]; sWk[i] = Wk[i];
    }
    for (int i = threadIdx.x; i < 6144; i += 256) sWv[i] = Wv[i];
    if (threadIdx.x < 64) {
        sWb[threadIdx.x] = Wb[threadIdx.x];
        sGm[threadIdx.x] = gam[threadIdx.x];
        sBt[threadIdx.x] = bet[threadIdx.x];
    }
    __syncthreads();

    const int lane = threadIdx.x & 31;
    const int warp = (blockIdx.x * blockDim.x + threadIdx.x) >> 5;
    const int nw   = (gridDim.x * blockDim.x) >> 5;
    const float bb0 = bb[0];

    for (int p = warp; p < MPTS; p += nw) {
        const float* gx = geo + (size_t)p * DD;
        float x0 = gx[lane], x1 = gx[lane + 32];

        // a = geo_row @ W_geo   (lane owns output cols lane, lane+32)
        float a0 = 0.f, a1 = 0.f;
#pragma unroll
        for (int i = 0; i < 32; i++) {
            float xv = __shfl_sync(0xffffffffu, x0, i);
            a0 = fmaf(xv, sWg[i * 64 + lane], a0);
            a1 = fmaf(xv, sWg[i * 64 + 32 + lane], a1);
        }
#pragma unroll
        for (int i = 0; i < 32; i++) {
            float xv = __shfl_sync(0xffffffffu, x1, i);
            a0 = fmaf(xv, sWg[(i + 32) * 64 + lane], a0);
            a1 = fmaf(xv, sWg[(i + 32) * 64 + 32 + lane], a1);
        }
        // layernorm + relu
        float mu = wsum(a0 + a1) * (1.f / 64.f);
        float d0 = a0 - mu, d1 = a1 - mu;
        float var = wsum(d0 * d0 + d1 * d1) * (1.f / 64.f);
        float rs = rsqrtf(var + 1e-5f);
        float q0 = fmaxf(fmaf(d0 * rs, sGm[lane],      sBt[lane]),      0.f);
        float q1 = fmaxf(fmaf(d1 * rs, sGm[lane + 32], sBt[lane + 32]), 0.f);

        // boundary logit -> lives at offset 13*M in concatenated output
        float bd = wsum(q0 * sWb[lane] + q1 * sWb[lane + 32]);
        long long boff = (long long)13 * MPTS + p;
        if (lane == 0 && boff < total) out[boff] = bd + bb0;

        // Qp = q @ Wq,  Kb = q @ Wk  (fused: same broadcast of q)
        float u0 = 0.f, u1 = 0.f, v0 = 0.f, v1 = 0.f;
#pragma unroll
        for (int i = 0; i < 32; i++) {
            float xv = __shfl_sync(0xffffffffu, q0, i);
            u0 = fmaf(xv, sWq[i * 64 + lane], u0);
            u1 = fmaf(xv, sWq[i * 64 + 32 + lane], u1);
            v0 = fmaf(xv, sWk[i * 64 + lane], v0);
            v1 = fmaf(xv, sWk[i * 64 + 32 + lane], v1);
        }
#pragma unroll
        for (int i = 0; i < 32; i++) {
            float xv = __shfl_sync(0xffffffffu, q1, i);
            u0 = fmaf(xv, sWq[(i + 32) * 64 + lane], u0);
            u1 = fmaf(xv, sWq[(i + 32) * 64 + 32 + lane], u1);
            v0 = fmaf(xv, sWk[(i + 32) * 64 + lane], v0);
            v1 = fmaf(xv, sWk[(i + 32) * 64 + 32 + lane], v1);
        }
        g_Qp[p * DD + lane] = u0;  g_Qp[p * DD + 32 + lane] = u1;
        g_Kb[p * DD + lane] = v0;  g_Kb[p * DD + 32 + lane] = v1;

        // Vb = sem_row(96) @ Wv(96x64)
        const float* sx = sem + (size_t)p * CSEM;
        float s0 = sx[lane], s1 = sx[lane + 32], s2 = sx[lane + 64];
        float w0 = 0.f, w1 = 0.f;
#pragma unroll
        for (int i = 0; i < 32; i++) {
            float xv = __shfl_sync(0xffffffffu, s0, i);
            w0 = fmaf(xv, sWv[i * 64 + lane], w0);
            w1 = fmaf(xv, sWv[i * 64 + 32 + lane], w1);
        }
#pragma unroll
        for (int i = 0; i < 32; i++) {
            float xv = __shfl_sync(0xffffffffu, s1, i);
            w0 = fmaf(xv, sWv[(i + 32) * 64 + lane], w0);
            w1 = fmaf(xv, sWv[(i + 32) * 64 + 32 + lane], w1);
        }
#pragma unroll
        for (int i = 0; i < 32; i++) {
            float xv = __shfl_sync(0xffffffffu, s2, i);
            w0 = fmaf(xv, sWv[(i + 64) * 64 + lane], w0);
            w1 = fmaf(xv, sWv[(i + 64) * 64 + 32 + lane], w1);
        }
        g_Vb[p * DD + lane] = w0;  g_Vb[p * DD + 32 + lane] = w1;
    }
}

// ---------------------------------------------------------------------------
// Kernel B: per-point gather attention + softmax + W_out/W_cls epilogue +
// all remaining outputs. neighbor_idx is INT32 (JAX x64 disabled).
// ---------------------------------------------------------------------------
__global__ void __launch_bounds__(256) kB(
    const int* __restrict__ coords, const int* __restrict__ nbr,
    const float* __restrict__ pe, const float* __restrict__ Wo,
    const float* __restrict__ bo, const float* __restrict__ Wc,
    const float* __restrict__ bc, float* __restrict__ out, long long total)
{
    __shared__ float sWo[4096];
    __shared__ float sPe[KN * 64];
    __shared__ float sWc[64 * 13];
    __shared__ float sBo[64];
    __shared__ float sBc[13];

    for (int i = threadIdx.x; i < 4096; i += 256) sWo[i] = Wo[i];
    for (int i = threadIdx.x; i < KN * 64; i += 256) sPe[i] = pe[i];
    for (int i = threadIdx.x; i < 64 * 13; i += 256) sWc[i] = Wc[i];
    if (threadIdx.x < 64) sBo[threadIdx.x] = bo[threadIdx.x];
    if (threadIdx.x < 13) sBc[threadIdx.x] = bc[threadIdx.x];
    __syncthreads();

    const int lane = threadIdx.x & 31;
    const int warp = (blockIdx.x * blockDim.x + threadIdx.x) >> 5;
    const int nw   = (gridDim.x * blockDim.x) >> 5;

    const long long off_log = 0;                       // [M,13]
    const long long off_aff = (long long)14 * MPTS;    // [M,27]  (after bdy [M,1])
    const long long off_ref = (long long)41 * MPTS;    // [M,64]
    const long long off_nbr = (long long)105 * MPTS;   // [M,27]
    const long long off_msk = (long long)132 * MPTS;   // [M,27]

    for (int p = warp; p < MPTS; p += nw) {
        float q0 = g_Qp[p * DD + lane], q1 = g_Qp[p * DD + 32 + lane];
        int cx = coords[3 * p], cy = coords[3 * p + 1], cz = coords[3 * p + 2];

        int myidx = 0, mypos = 0, myvalid = 0;
        if (lane < KN) {
            myidx = nbr[(size_t)p * KN + lane];
            int rx = coords[3 * myidx]     - cx;
            int ry = coords[3 * myidx + 1] - cy;
            int rz = coords[3 * myidx + 2] - cz;
            int mx = max(abs(rx), max(abs(ry), abs(rz)));
            myvalid = (mx <= 1);
            int px = min(max(rx + 1, 0), 2);
            int py = min(max(ry + 1, 0), 2);
            int pz = min(max(rz + 1, 0), 2);
            mypos = px * 9 + py * 3 + pz;
        }

        float mylogit = -1e30f;
#pragma unroll
        for (int k = 0; k < KN; k++) {
            int idx = __shfl_sync(0xffffffffu, myidx, k);
            int pos = __shfl_sync(0xffffffffu, mypos, k);
            int vld = __shfl_sync(0xffffffffu, myvalid, k);
            const float* kb = g_Kb + (size_t)idx * DD;
            const float* pr = sPe + pos * 64;
            float part = q0 * (kb[lane] + pr[lane]) +
                         q1 * (kb[lane + 32] + pr[lane + 32]);
            float lg = wsum(part);
            lg = vld ? lg * 0.125f : -10000.0f;
            if (lane == k) mylogit = lg;
        }

        // softmax over 27 (lanes >=27 hold -1e30 -> exp underflows to 0)
        float mx = wmax(mylogit);
        float e = __expf(mylogit - mx);
        float ssum = wsum(e);
        float aff = e / ssum;

        // refined = sum_k aff_k * Vb[idx_k] + Vb[p]
        float r0 = g_Vb[p * DD + lane], r1 = g_Vb[p * DD + 32 + lane];
#pragma unroll
        for (int k = 0; k < KN; k++) {
            float av = __shfl_sync(0xffffffffu, aff, k);
            int idx = __shfl_sync(0xffffffffu, myidx, k);
            const float* vb = g_Vb + (size_t)idx * DD;
            r0 = fmaf(av, vb[lane], r0);
            r1 = fmaf(av, vb[lane + 32], r1);
        }

        if (lane < KN) {
            long long oa = off_aff + (long long)p * KN + lane;
            long long on = off_nbr + (long long)p * KN + lane;
            long long om = off_msk + (long long)p * KN + lane;
            if (oa < total) out[oa] = aff;
            if (on < total) out[on] = (float)myidx;
            if (om < total) out[om] = myvalid ? 1.f : 0.f;
        }

        // refined_feat = r @ Wo + bo
        float f0 = sBo[lane], f1 = sBo[lane + 32];
#pragma unroll
        for (int i = 0; i < 32; i++) {
            float rv = __shfl_sync(0xffffffffu, r0, i);
            f0 = fmaf(rv, sWo[i * 64 + lane], f0);
            f1 = fmaf(rv, sWo[i * 64 + 32 + lane], f1);
        }
#pragma unroll
        for (int i = 0; i < 32; i++) {
            float rv = __shfl_sync(0xffffffffu, r1, i);
            f0 = fmaf(rv, sWo[(i + 32) * 64 + lane], f0);
            f1 = fmaf(rv, sWo[(i + 32) * 64 + 32 + lane], f1);
        }
        long long orf = off_ref + (long long)p * DD + lane;
        if (orf < total) out[orf] = f0;
        if (orf + 32 < total) out[orf + 32] = f1;

        // logits = f @ Wc + bc   (13 classes -> lanes 0..12)
        float c = (lane < 13) ? sBc[lane] : 0.f;
#pragma unroll
        for (int i = 0; i < 32; i++) {
            float fv = __shfl_sync(0xffffffffu, f0, i);
            if (lane < 13) c = fmaf(fv, sWc[i * 13 + lane], c);
        }
#pragma unroll
        for (int i = 0; i < 32; i++) {
            float fv = __shfl_sync(0xffffffffu, f1, i);
            if (lane < 13) c = fmaf(fv, sWc[(i + 32) * 13 + lane], c);
        }
        long long ol = off_log + (long long)p * 13 + lane;
        if (lane < 13 && ol < total) out[ol] = c;
    }
}

extern "C" void kernel_launch(void* const* d_in, const int* in_sizes, int n_in,
                              void* d_out, int out_size)
{
    const float* geo    = (const float*)d_in[0];
    const float* sem    = (const float*)d_in[1];
    const int*   coords = (const int*)d_in[2];
    const int*   nbr    = (const int*)d_in[3];   // JAX x64 off -> int32
    const float* Wg     = (const float*)d_in[4];
    const float* gam    = (const float*)d_in[5];
    const float* bet    = (const float*)d_in[6];
    const float* Wb     = (const float*)d_in[7];
    const float* bb     = (const float*)d_in[8];
    const float* Wq     = (const float*)d_in[9];
    const float* Wk     = (const float*)d_in[10];
    const float* Wv     = (const float*)d_in[11];
    const float* pe     = (const float*)d_in[12];
    const float* Wo     = (const float*)d_in[13];
    const float* bo     = (const float*)d_in[14];
    const float* Wc     = (const float*)d_in[15];
    const float* bc     = (const float*)d_in[16];
    float* out = (float*)d_out;
    long long total = (long long)out_size;

    const int smemA = 18624 * 4;  // 74496 B > 48KB default -> opt-in
    cudaFuncSetAttribute(kA, cudaFuncAttributeMaxDynamicSharedMemorySize, smemA);

    kA<<<444, 256, smemA>>>(geo, sem, Wg, gam, bet, Wb, bb, Wq, Wk, Wv,
                            out, total);
    kB<<<1184, 256>>>(coords, nbr, pe, Wo, bo, Wc, bc, out, total);
}

// round 3
// speedup vs baseline: 1.3916x; 1.3916x over previous
#include <cuda_runtime.h>

#define MPTS 100000
#define KN   27
#define DD   64
#define CSEM 96

// Scratch (__device__ globals; g_Qp is reused as `refined` storage by kB)
__device__ float g_Qp[MPTS * DD];
__device__ float g_Kb[MPTS * DD];
__device__ float g_Vb[MPTS * DD];

__device__ __forceinline__ float wsum(float v) {
#pragma unroll
    for (int o = 16; o; o >>= 1) v += __shfl_xor_sync(0xffffffffu, v, o);
    return v;
}
__device__ __forceinline__ float wmax(float v) {
#pragma unroll
    for (int o = 16; o; o >>= 1) v = fmaxf(v, __shfl_xor_sync(0xffffffffu, v, o));
    return v;
}

// ---------------------------------------------------------------------------
// Kernel A: 4 points per warp.
//   Q_geo = relu(LN(geo@Wg)); bdy; Qp=Q@Wq; Kb=Q@Wk; Vb=sem@Wv
// Each weight LDS feeds 4 FMAs (one per point).
// ---------------------------------------------------------------------------
__global__ void __launch_bounds__(256) kA(
    const float* __restrict__ geo, const float* __restrict__ sem,
    const float* __restrict__ Wg, const float* __restrict__ gam,
    const float* __restrict__ bet, const float* __restrict__ Wb,
    const float* __restrict__ bb, const float* __restrict__ Wq,
    const float* __restrict__ Wk, const float* __restrict__ Wv,
    float* __restrict__ out, long long total)
{
    extern __shared__ float sm[];
    float* sWg = sm;
    float* sWq = sm + 4096;
    float* sWk = sm + 8192;
    float* sWv = sm + 12288;
    float* sWb = sm + 18432;
    float* sGm = sm + 18496;
    float* sBt = sm + 18560;

    for (int i = threadIdx.x; i < 4096; i += 256) {
        sWg[i] = Wg[i]; sWq[i] = Wq[i]; sWk[i] = Wk[i];
    }
    for (int i = threadIdx.x; i < 6144; i += 256) sWv[i] = Wv[i];
    if (threadIdx.x < 64) {
        sWb[threadIdx.x] = Wb[threadIdx.x];
        sGm[threadIdx.x] = gam[threadIdx.x];
        sBt[threadIdx.x] = bet[threadIdx.x];
    }
    __syncthreads();

    const int lane = threadIdx.x & 31;
    const int warp = (blockIdx.x * blockDim.x + threadIdx.x) >> 5;
    const int nw   = (gridDim.x * blockDim.x) >> 5;
    const float bb0 = bb[0];
    const float gm0 = sGm[lane], gm1 = sGm[lane + 32];
    const float bt0 = sBt[lane], bt1 = sBt[lane + 32];
    const float wb0 = sWb[lane], wb1 = sWb[lane + 32];

    // MPTS % 4 == 0, stride keeps alignment -> no tail handling needed
    for (int p4 = warp * 4; p4 < MPTS; p4 += nw * 4) {
        float x0[4], x1[4];
#pragma unroll
        for (int j = 0; j < 4; j++) {
            const float* gx = geo + (size_t)(p4 + j) * DD;
            x0[j] = gx[lane]; x1[j] = gx[lane + 32];
        }

        float a0[4] = {0,0,0,0}, a1[4] = {0,0,0,0};
#pragma unroll
        for (int i = 0; i < 32; i++) {
            float w0 = sWg[i * 64 + lane], w1 = sWg[i * 64 + 32 + lane];
#pragma unroll
            for (int j = 0; j < 4; j++) {
                float xv = __shfl_sync(0xffffffffu, x0[j], i);
                a0[j] = fmaf(xv, w0, a0[j]);
                a1[j] = fmaf(xv, w1, a1[j]);
            }
        }
#pragma unroll
        for (int i = 0; i < 32; i++) {
            float w0 = sWg[(i + 32) * 64 + lane], w1 = sWg[(i + 32) * 64 + 32 + lane];
#pragma unroll
            for (int j = 0; j < 4; j++) {
                float xv = __shfl_sync(0xffffffffu, x1[j], i);
                a0[j] = fmaf(xv, w0, a0[j]);
                a1[j] = fmaf(xv, w1, a1[j]);
            }
        }

        // LayerNorm + ReLU + bdy per point (4 independent reduce chains = ILP)
        float q0[4], q1[4];
#pragma unroll
        for (int j = 0; j < 4; j++) {
            float mu = wsum(a0[j] + a1[j]) * (1.f / 64.f);
            float d0 = a0[j] - mu, d1 = a1[j] - mu;
            float var = wsum(d0 * d0 + d1 * d1) * (1.f / 64.f);
            float rs = rsqrtf(var + 1e-5f);
            q0[j] = fmaxf(fmaf(d0 * rs, gm0, bt0), 0.f);
            q1[j] = fmaxf(fmaf(d1 * rs, gm1, bt1), 0.f);
            float bd = wsum(q0[j] * wb0 + q1[j] * wb1);
            long long boff = (long long)13 * MPTS + (p4 + j);
            if (lane == 0 && boff < total) out[boff] = bd + bb0;
        }

        // Qp / Kb (each LDS pair feeds 8 FMAs)
        float u0[4] = {0,0,0,0}, u1[4] = {0,0,0,0};
        float v0[4] = {0,0,0,0}, v1[4] = {0,0,0,0};
#pragma unroll
        for (int i = 0; i < 32; i++) {
            float wq0 = sWq[i * 64 + lane], wq1 = sWq[i * 64 + 32 + lane];
            float wk0 = sWk[i * 64 + lane], wk1 = sWk[i * 64 + 32 + lane];
#pragma unroll
            for (int j = 0; j < 4; j++) {
                float xv = __shfl_sync(0xffffffffu, q0[j], i);
                u0[j] = fmaf(xv, wq0, u0[j]); u1[j] = fmaf(xv, wq1, u1[j]);
                v0[j] = fmaf(xv, wk0, v0[j]); v1[j] = fmaf(xv, wk1, v1[j]);
            }
        }
#pragma unroll
        for (int i = 0; i < 32; i++) {
            float wq0 = sWq[(i + 32) * 64 + lane], wq1 = sWq[(i + 32) * 64 + 32 + lane];
            float wk0 = sWk[(i + 32) * 64 + lane], wk1 = sWk[(i + 32) * 64 + 32 + lane];
#pragma unroll
            for (int j = 0; j < 4; j++) {
                float xv = __shfl_sync(0xffffffffu, q1[j], i);
                u0[j] = fmaf(xv, wq0, u0[j]); u1[j] = fmaf(xv, wq1, u1[j]);
                v0[j] = fmaf(xv, wk0, v0[j]); v1[j] = fmaf(xv, wk1, v1[j]);
            }
        }
#pragma unroll
        for (int j = 0; j < 4; j++) {
            int p = p4 + j;
            g_Qp[p * DD + lane] = u0[j];  g_Qp[p * DD + 32 + lane] = u1[j];
            g_Kb[p * DD + lane] = v0[j];  g_Kb[p * DD + 32 + lane] = v1[j];
        }

        // Vb = sem(96) @ Wv(96x64)
        float s0[4], s1[4], s2[4];
#pragma unroll
        for (int j = 0; j < 4; j++) {
            const float* sx = sem + (size_t)(p4 + j) * CSEM;
            s0[j] = sx[lane]; s1[j] = sx[lane + 32]; s2[j] = sx[lane + 64];
        }
        float w0a[4] = {0,0,0,0}, w1a[4] = {0,0,0,0};
#pragma unroll
        for (int i = 0; i < 32; i++) {
            float wv0 = sWv[i * 64 + lane], wv1 = sWv[i * 64 + 32 + lane];
#pragma unroll
            for (int j = 0; j < 4; j++) {
                float xv = __shfl_sync(0xffffffffu, s0[j], i);
                w0a[j] = fmaf(xv, wv0, w0a[j]); w1a[j] = fmaf(xv, wv1, w1a[j]);
            }
        }
#pragma unroll
        for (int i = 0; i < 32; i++) {
            float wv0 = sWv[(i + 32) * 64 + lane], wv1 = sWv[(i + 32) * 64 + 32 + lane];
#pragma unroll
            for (int j = 0; j < 4; j++) {
                float xv = __shfl_sync(0xffffffffu, s1[j], i);
                w0a[j] = fmaf(xv, wv0, w0a[j]); w1a[j] = fmaf(xv, wv1, w1a[j]);
            }
        }
#pragma unroll
        for (int i = 0; i < 32; i++) {
            float wv0 = sWv[(i + 64) * 64 + lane], wv1 = sWv[(i + 64) * 64 + 32 + lane];
#pragma unroll
            for (int j = 0; j < 4; j++) {
                float xv = __shfl_sync(0xffffffffu, s2[j], i);
                w0a[j] = fmaf(xv, wv0, w0a[j]); w1a[j] = fmaf(xv, wv1, w1a[j]);
            }
        }
#pragma unroll
        for (int j = 0; j < 4; j++) {
            int p = p4 + j;
            g_Vb[p * DD + lane] = w0a[j];  g_Vb[p * DD + 32 + lane] = w1a[j];
        }
    }
}

// ---------------------------------------------------------------------------
// Kernel B: attention only, 2 points per warp (interleaved reduce chains).
// Writes refined into g_Qp (row p is dead after q is loaded).
// ---------------------------------------------------------------------------
__global__ void __launch_bounds__(256) kB(
    const int* __restrict__ coords, const int* __restrict__ nbr,
    const float* __restrict__ pe, float* __restrict__ out, long long total)
{
    __shared__ float sPe[KN * 64];
    for (int i = threadIdx.x; i < KN * 64; i += 256) sPe[i] = pe[i];
    __syncthreads();

    const int lane = threadIdx.x & 31;
    const int warp = (blockIdx.x * blockDim.x + threadIdx.x) >> 5;
    const int nw   = (gridDim.x * blockDim.x) >> 5;

    const long long off_aff = (long long)14 * MPTS;    // [M,27]
    const long long off_nbr = (long long)105 * MPTS;   // [M,27]
    const long long off_msk = (long long)132 * MPTS;   // [M,27]

    for (int p2 = warp * 2; p2 < MPTS; p2 += nw * 2) {
        const int pA = p2, pB = p2 + 1;
        float qA0 = g_Qp[pA * DD + lane], qA1 = g_Qp[pA * DD + 32 + lane];
        float qB0 = g_Qp[pB * DD + lane], qB1 = g_Qp[pB * DD + 32 + lane];

        int cAx = coords[3 * pA], cAy = coords[3 * pA + 1], cAz = coords[3 * pA + 2];
        int cBx = coords[3 * pB], cBy = coords[3 * pB + 1], cBz = coords[3 * pB + 2];

        int idxA = 0, metaA = 0, idxB = 0, metaB = 0;   // meta = pos | (valid<<8)
        if (lane < KN) {
            idxA = nbr[(size_t)pA * KN + lane];
            int rx = coords[3 * idxA] - cAx, ry = coords[3 * idxA + 1] - cAy,
                rz = coords[3 * idxA + 2] - cAz;
            int vld = (max(abs(rx), max(abs(ry), abs(rz))) <= 1);
            int pos = min(max(rx + 1, 0), 2) * 9 + min(max(ry + 1, 0), 2) * 3
                    + min(max(rz + 1, 0), 2);
            metaA = pos | (vld << 8);
            idxB = nbr[(size_t)pB * KN + lane];
            rx = coords[3 * idxB] - cBx; ry = coords[3 * idxB + 1] - cBy;
            rz = coords[3 * idxB + 2] - cBz;
            vld = (max(abs(rx), max(abs(ry), abs(rz))) <= 1);
            pos = min(max(rx + 1, 0), 2) * 9 + min(max(ry + 1, 0), 2) * 3
                + min(max(rz + 1, 0), 2);
            metaB = pos | (vld << 8);
        }

        float logitA = -1e30f, logitB = -1e30f;
#pragma unroll
        for (int k = 0; k < KN; k++) {
            int ia = __shfl_sync(0xffffffffu, idxA, k);
            int ma = __shfl_sync(0xffffffffu, metaA, k);
            int ib = __shfl_sync(0xffffffffu, idxB, k);
            int mb = __shfl_sync(0xffffffffu, metaB, k);
            const float* kba = g_Kb + (size_t)ia * DD;
            const float* kbb = g_Kb + (size_t)ib * DD;
            const float* pra = sPe + (ma & 0xff) * 64;
            const float* prb = sPe + (mb & 0xff) * 64;
            float pa = qA0 * (kba[lane] + pra[lane]) +
                       qA1 * (kba[lane + 32] + pra[lane + 32]);
            float pb = qB0 * (kbb[lane] + prb[lane]) +
                       qB1 * (kbb[lane + 32] + prb[lane + 32]);
#pragma unroll
            for (int o = 16; o; o >>= 1) {
                pa += __shfl_xor_sync(0xffffffffu, pa, o);
                pb += __shfl_xor_sync(0xffffffffu, pb, o);
            }
            float la = (ma >> 8) ? pa * 0.125f : -10000.0f;
            float lb = (mb >> 8) ? pb * 0.125f : -10000.0f;
            if (lane == k) { logitA = la; logitB = lb; }
        }

        // softmax (lanes >= 27 hold -1e30 -> exp -> 0)
        float mA = logitA, mB = logitB;
#pragma unroll
        for (int o = 16; o; o >>= 1) {
            mA = fmaxf(mA, __shfl_xor_sync(0xffffffffu, mA, o));
            mB = fmaxf(mB, __shfl_xor_sync(0xffffffffu, mB, o));
        }
        float eA = __expf(logitA - mA), eB = __expf(logitB - mB);
        float sA = eA, sB = eB;
#pragma unroll
        for (int o = 16; o; o >>= 1) {
            sA += __shfl_xor_sync(0xffffffffu, sA, o);
            sB += __shfl_xor_sync(0xffffffffu, sB, o);
        }
        float affA = eA / sA, affB = eB / sB;

        // refined = Vb[p] + sum_k aff_k * Vb[idx_k]
        float rA0 = g_Vb[pA * DD + lane], rA1 = g_Vb[pA * DD + 32 + lane];
        float rB0 = g_Vb[pB * DD + lane], rB1 = g_Vb[pB * DD + 32 + lane];
#pragma unroll
        for (int k = 0; k < KN; k++) {
            float aa = __shfl_sync(0xffffffffu, affA, k);
            int   ia = __shfl_sync(0xffffffffu, idxA, k);
            float ab = __shfl_sync(0xffffffffu, affB, k);
            int   ib = __shfl_sync(0xffffffffu, idxB, k);
            const float* va = g_Vb + (size_t)ia * DD;
            const float* vb = g_Vb + (size_t)ib * DD;
            rA0 = fmaf(aa, va[lane], rA0); rA1 = fmaf(aa, va[lane + 32], rA1);
            rB0 = fmaf(ab, vb[lane], rB0); rB1 = fmaf(ab, vb[lane + 32], rB1);
        }

        // store refined into g_Qp (dead storage), outputs aff/nbr/msk
        g_Qp[pA * DD + lane] = rA0;  g_Qp[pA * DD + 32 + lane] = rA1;
        g_Qp[pB * DD + lane] = rB0;  g_Qp[pB * DD + 32 + lane] = rB1;

        if (lane < KN) {
            long long a = (long long)pA * KN + lane;
            long long b = (long long)pB * KN + lane;
            if (off_aff + b < total) {
                out[off_aff + a] = affA;            out[off_aff + b] = affB;
                out[off_nbr + a] = (float)idxA;     out[off_nbr + b] = (float)idxB;
                out[off_msk + a] = (metaA >> 8) ? 1.f : 0.f;
                out[off_msk + b] = (metaB >> 8) ? 1.f : 0.f;
            }
        }
    }
}

// ---------------------------------------------------------------------------
// Kernel C: epilogue, 4 points per warp: f = refined@Wo + bo; logits = f@Wc + bc
// ---------------------------------------------------------------------------
__global__ void __launch_bounds__(256) kC(
    const float* __restrict__ Wo, const float* __restrict__ bo,
    const float* __restrict__ Wc, const float* __restrict__ bc,
    float* __restrict__ out, long long total)
{
    __shared__ float sWo[4096];
    __shared__ float sWc[64 * 13];
    __shared__ float sBo[64];
    __shared__ float sBc[16];
    for (int i = threadIdx.x; i < 4096; i += 256) sWo[i] = Wo[i];
    for (int i = threadIdx.x; i < 64 * 13; i += 256) sWc[i] = Wc[i];
    if (threadIdx.x < 64) sBo[threadIdx.x] = bo[threadIdx.x];
    if (threadIdx.x < 16) sBc[threadIdx.x] = (threadIdx.x < 13) ? bc[threadIdx.x] : 0.f;
    __syncthreads();

    const int lane = threadIdx.x & 31;
    const int warp = (blockIdx.x * blockDim.x + threadIdx.x) >> 5;
    const int nw   = (gridDim.x * blockDim.x) >> 5;
    const long long off_ref = (long long)41 * MPTS;    // [M,64]

    for (int p4 = warp * 4; p4 < MPTS; p4 += nw * 4) {
        float r0[4], r1[4];
#pragma unroll
        for (int j = 0; j < 4; j++) {
            r0[j] = g_Qp[(p4 + j) * DD + lane];
            r1[j] = g_Qp[(p4 + j) * DD + 32 + lane];
        }
        float f0[4], f1[4];
#pragma unroll
        for (int j = 0; j < 4; j++) { f0[j] = sBo[lane]; f1[j] = sBo[lane + 32]; }
#pragma unroll
        for (int i = 0; i < 32; i++) {
            float w0 = sWo[i * 64 + lane], w1 = sWo[i * 64 + 32 + lane];
#pragma unroll
            for (int j = 0; j < 4; j++) {
                float rv = __shfl_sync(0xffffffffu, r0[j], i);
                f0[j] = fmaf(rv, w0, f0[j]); f1[j] = fmaf(rv, w1, f1[j]);
            }
        }
#pragma unroll
        for (int i = 0; i < 32; i++) {
            float w0 = sWo[(i + 32) * 64 + lane], w1 = sWo[(i + 32) * 64 + 32 + lane];
#pragma unroll
            for (int j = 0; j < 4; j++) {
                float rv = __shfl_sync(0xffffffffu, r1[j], i);
                f0[j] = fmaf(rv, w0, f0[j]); f1[j] = fmaf(rv, w1, f1[j]);
            }
        }
#pragma unroll
        for (int j = 0; j < 4; j++) {
            long long o = off_ref + (long long)(p4 + j) * DD + lane;
            if (o + 32 < total) { out[o] = f0[j]; out[o + 32] = f1[j]; }
        }

        // logits (lanes 0..12)
        float c[4];
#pragma unroll
        for (int j = 0; j < 4; j++) c[j] = (lane < 13) ? sBc[lane] : 0.f;
#pragma unroll
        for (int i = 0; i < 32; i++) {
            float wv = (lane < 13) ? sWc[i * 13 + lane] : 0.f;
#pragma unroll
            for (int j = 0; j < 4; j++) {
                float fv = __shfl_sync(0xffffffffu, f0[j], i);
                c[j] = fmaf(fv, wv, c[j]);
            }
        }
#pragma unroll
        for (int i = 0; i < 32; i++) {
            float wv = (lane < 13) ? sWc[(i + 32) * 13 + lane] : 0.f;
#pragma unroll
            for (int j = 0; j < 4; j++) {
                float fv = __shfl_sync(0xffffffffu, f1[j], i);
                c[j] = fmaf(fv, wv, c[j]);
            }
        }
#pragma unroll
        for (int j = 0; j < 4; j++) {
            long long o = (long long)(p4 + j) * 13 + lane;
            if (lane < 13 && o < total) out[o] = c[j];
        }
    }
}

extern "C" void kernel_launch(void* const* d_in, const int* in_sizes, int n_in,
                              void* d_out, int out_size)
{
    const float* geo    = (const float*)d_in[0];
    const float* sem    = (const float*)d_in[1];
    const int*   coords = (const int*)d_in[2];
    const int*   nbr    = (const int*)d_in[3];   // int32 (JAX x64 off)
    const float* Wg     = (const float*)d_in[4];
    const float* gam    = (const float*)d_in[5];
    const float* bet    = (const float*)d_in[6];
    const float* Wb     = (const float*)d_in[7];
    const float* bb     = (const float*)d_in[8];
    const float* Wq     = (const float*)d_in[9];
    const float* Wk     = (const float*)d_in[10];
    const float* Wv     = (const float*)d_in[11];
    const float* pe     = (const float*)d_in[12];
    const float* Wo     = (const float*)d_in[13];
    const float* bo     = (const float*)d_in[14];
    const float* Wc     = (const float*)d_in[15];
    const float* bc     = (const float*)d_in[16];
    float* out = (float*)d_out;
    long long total = (long long)out_size;

    const int smemA = 18624 * 4;
    cudaFuncSetAttribute(kA, cudaFuncAttributeMaxDynamicSharedMemorySize, smemA);

    kA<<<444, 256, smemA>>>(geo, sem, Wg, gam, bet, Wb, bb, Wq, Wk, Wv, out, total);
    kB<<<1184, 256>>>(coords, nbr, pe, out, total);
    kC<<<592, 256>>>(Wo, bo, Wc, bc, out, total);
}